// round 10
// baseline (speedup 1.0000x reference)
#include <cuda_runtime.h>
#include <math.h>

#define BB   32768
#define NQUAD 8192
#define NN   27
#define HID  128
#define SINK_ITERS 20

// Staging buffer for transposed scores: [b][k][n] (pre-tau, pre-exp).
__device__ float g_scores[(size_t)BB * NN * NN];

// ---------------- shared memory layout (floats) ----------------
#define OFF_W2   0          // 128*128
#define OFF_W1   16384      // 4*128
#define OFF_B1   16896
#define OFF_B2   17024
#define OFF_G2   17152
#define OFF_BB2  17280
#define OFF_LN1  17408      // 8
#define OFF_M    17416      // 108
#define OFF_P    17524      // 27*132 = 3564 ; stride 132 -> conflict-free LDS.128 spread
#define P_STRIDE 132
#define OFF_BAT  21088
// per-batch sub-offsets
#define BO_A 0               // 729 (pad 732)
#define BO_X 732             // 108 (pad 112)
#define BO_R 844             // 27*128
#define BO_H 4300            // 27*128
#define BO_SC 7756           // 27*29 = 783
#define PB   8540
#define SMEM_FLOATS (OFF_BAT + 4*PB)
#define SMEM_BYTES  (SMEM_FLOATS * 4)   // 220,992 B

// packed fp32x2 ops (bit-exact IEEE fp32 per component)
#define FFMA2ACC(d,a,b) asm("fma.rn.f32x2 %0, %1, %2, %0;" : "+l"(d) : "l"(a), "l"(b))
#define PADD(d,a,b)     asm("add.rn.f32x2 %0, %1, %2;" : "=l"(d) : "l"(a), "l"(b))
#define PMUL(d,a,b)     asm("mul.rn.f32x2 %0, %1, %2;" : "=l"(d) : "l"(a), "l"(b))

__device__ __forceinline__ unsigned long long dup2(float x) {
    unsigned long long r;
    asm("mov.b64 %0, {%1, %2};" : "=l"(r) : "f"(x), "f"(x));
    return r;
}
__device__ __forceinline__ unsigned long long pk2(float x, float y) {
    unsigned long long r;
    asm("mov.b64 %0, {%1, %2};" : "=l"(r) : "f"(x), "f"(y));
    return r;
}
__device__ __forceinline__ float2 unpk(unsigned long long v) {
    float2 f;
    asm("mov.b64 {%0, %1}, %2;" : "=f"(f.x), "=f"(f.y) : "l"(v));
    return f;
}
__device__ __forceinline__ float rcpa(float x) {
    float r;
    asm("rcp.approx.f32 %0, %1;" : "=f"(r) : "f"(x));
    return r;
}

// ---- P3: h = relu_r @ W2 + b2, NR rows (n = w2 + 2t), lane jq owns j=4jq..4jq+3 ----
template<int NR>
__device__ __forceinline__ void p3_rows(const float* __restrict__ srb,
                                        float* __restrict__ shb,
                                        const float* __restrict__ sW2,
                                        const float* __restrict__ sb2,
                                        int w2, int jq)
{
    const ulonglong2* W2v = (const ulonglong2*)sW2;
    unsigned long long aL[NR], aH[NR];
#pragma unroll
    for (int t = 0; t < NR; t++) { aL[t] = 0ull; aH[t] = 0ull; }
#pragma unroll 1
    for (int i = 0; i < HID; i += 4) {
        ulonglong2 w0 = W2v[(i + 0) * 32 + jq];
        ulonglong2 w1 = W2v[(i + 1) * 32 + jq];
        ulonglong2 w2v = W2v[(i + 2) * 32 + jq];
        ulonglong2 w3 = W2v[(i + 3) * 32 + jq];
#pragma unroll
        for (int t = 0; t < NR; t++) {
            const int n = w2 + 2 * t;
            float4 rq = *(const float4*)(srb + n * HID + i);     // broadcast LDS.128
            unsigned long long r0 = dup2(rq.x), r1 = dup2(rq.y);
            unsigned long long r2 = dup2(rq.z), r3 = dup2(rq.w);
            FFMA2ACC(aL[t], r0, w0.x);  FFMA2ACC(aH[t], r0, w0.y);
            FFMA2ACC(aL[t], r1, w1.x);  FFMA2ACC(aH[t], r1, w1.y);
            FFMA2ACC(aL[t], r2, w2v.x); FFMA2ACC(aH[t], r2, w2v.y);
            FFMA2ACC(aL[t], r3, w3.x);  FFMA2ACC(aH[t], r3, w3.y);
        }
    }
    float4 bb = ((const float4*)sb2)[jq];
#pragma unroll
    for (int t = 0; t < NR; t++) {
        const int n = w2 + 2 * t;
        float2 lo = unpk(aL[t]), hi = unpk(aH[t]);
        float4 o;
        o.x = lo.x + bb.x; o.y = lo.y + bb.y;
        o.z = hi.x + bb.z; o.w = hi.y + bb.w;
        *(float4*)(shb + n * HID + 4 * jq) = o;
    }
}

// ---- P5: scores[n][k] = H[n]·protos[k], lane = k, NR rows; store ssc[k][n] ----
template<int NR>
__device__ __forceinline__ void p5_rows(const float* __restrict__ shb,
                                        const float* __restrict__ sP,
                                        float* __restrict__ ssc,
                                        int w2, int k, bool kvalid)
{
    const int kk = kvalid ? k : (NN - 1);
    const ulonglong2* Pv = (const ulonglong2*)sP;    // row stride 132 fl = 33 ull2
    unsigned long long acc[NR];
#pragma unroll
    for (int t = 0; t < NR; t++) acc[t] = 0ull;
#pragma unroll 1
    for (int jq = 0; jq < 32; jq++) {
        ulonglong2 pv = Pv[kk * 33 + jq];            // conflict-free spread LDS.128
#pragma unroll
        for (int t = 0; t < NR; t++) {
            const int n = w2 + 2 * t;
            ulonglong2 hv = *(const ulonglong2*)(shb + n * HID + 4 * jq);  // broadcast
            FFMA2ACC(acc[t], hv.x, pv.x);
            FFMA2ACC(acc[t], hv.y, pv.y);
        }
    }
    if (kvalid) {
#pragma unroll
        for (int t = 0; t < NR; t++) {
            float2 s = unpk(acc[t]);
            ssc[k * 29 + (w2 + 2 * t)] = s.x + s.y;
        }
    }
}

__global__ void __launch_bounds__(256, 1)
k1_scores(const float* __restrict__ A,
          const float* __restrict__ m_,
          const float* __restrict__ ln1_g, const float* __restrict__ ln1_b,
          const float* __restrict__ W1,    const float* __restrict__ b1,
          const float* __restrict__ W2,    const float* __restrict__ b2,
          const float* __restrict__ ln2_g, const float* __restrict__ ln2_b,
          const float* __restrict__ protos)
{
    extern __shared__ float sm[];
    const int tid  = threadIdx.x;
    const int lane = tid & 31;
    const int q    = tid >> 6;          // which batch of the quad (0..3)
    const int htid = tid & 63;          // thread id within the 64-thread quarter
    const int w2   = (tid >> 5) & 1;    // warp within quarter: even/odd rows

    // ---- one-time parameter staging ----
    for (int i = tid; i < HID * HID; i += 256) sm[OFF_W2 + i] = W2[i];
    for (int i = tid; i < 4 * HID; i += 256)   sm[OFF_W1 + i] = W1[i];
    if (tid < HID) {
        sm[OFF_B1 + tid]  = b1[tid];
        sm[OFF_B2 + tid]  = b2[tid];
        sm[OFF_G2 + tid]  = ln2_g[tid];
        sm[OFF_BB2 + tid] = ln2_b[tid];
    }
    if (tid < 4) { sm[OFF_LN1 + tid] = ln1_g[tid]; sm[OFF_LN1 + 4 + tid] = ln1_b[tid]; }
    for (int i = tid; i < NN * HID; i += 256)
        sm[OFF_P + (i >> 7) * P_STRIDE + (i & 127)] = protos[i];
    __syncthreads();

    // static scatter map for A prefetch (idx -> (batch-in-quad, offset))
    int jj[12], oo[12];
#pragma unroll
    for (int u = 0; u < 12; u++) {
        int idx = tid + 256 * u;
        jj[u] = idx / (NN * NN);
        oo[u] = idx - jj[u] * (NN * NN);
    }

    // ---- software pipeline: prefetch A/m for the current quad into registers ----
    float pf[12];
    float mreg = 0.f;
    int bq = blockIdx.x;
    {
        const float* src = A + (size_t)bq * (4 * NN * NN);
#pragma unroll
        for (int u = 0; u < 12; u++) {
            int idx = tid + 256 * u;
            pf[u] = (idx < 4 * NN * NN) ? src[idx] : 0.f;
        }
        if (tid < 4 * NN) mreg = m_[(size_t)bq * 4 * NN + tid];
    }

    for (; bq < NQUAD; bq += (int)gridDim.x) {
#pragma unroll
        for (int u = 0; u < 12; u++) {
            int idx = tid + 256 * u;
            if (idx < 4 * NN * NN)
                sm[OFF_BAT + jj[u] * PB + BO_A + oo[u]] = pf[u];
        }
        if (tid < 4 * NN) sm[OFF_M + tid] = mreg;
        __syncthreads();

        // prefetch next quad while this one computes
        {
            int bqn = bq + (int)gridDim.x;
            if (bqn < NQUAD) {
                const float* src = A + (size_t)bqn * (4 * NN * NN);
#pragma unroll
                for (int u = 0; u < 12; u++) {
                    int idx = tid + 256 * u;
                    pf[u] = (idx < 4 * NN * NN) ? src[idx] : 0.f;
                }
                if (tid < 4 * NN) mreg = m_[(size_t)bqn * 4 * NN + tid];
            }
        }

        float* sB  = sm + OFF_BAT + q * PB;
        float* sA  = sB + BO_A;
        float* sx  = sB + BO_X;
        float* sr  = sB + BO_R;
        float* sh  = sB + BO_H;
        float* ssc = sB + BO_SC;

        // ---- P1: features + LN1 (27 threads per quarter) ----
        if (htid < NN) {
            const int n = htid;
            float s = 0.f, t1 = 0.f, t2 = 0.f;
#pragma unroll
            for (int j = 0; j < NN; j++) {
                float a = sA[n * NN + j];
                s += a;
                float v = (j == n) ? 0.0f : a;
                if (v > t1) { t2 = t1; t1 = v; }
                else if (v > t2) { t2 = v; }
            }
            float f0 = log1pf(s);
            float f3 = sm[OFF_M + q * NN + n];
            float mu = 0.25f * (f0 + t1 + t2 + f3);
            float d0 = f0 - mu, d1 = t1 - mu, d2 = t2 - mu, d3 = f3 - mu;
            float var = 0.25f * (d0 * d0 + d1 * d1 + d2 * d2 + d3 * d3);
            float rs = rsqrtf(var + 1e-5f);
            sx[n * 4 + 0] = d0 * rs * sm[OFF_LN1 + 0] + sm[OFF_LN1 + 4];
            sx[n * 4 + 1] = d1 * rs * sm[OFF_LN1 + 1] + sm[OFF_LN1 + 5];
            sx[n * 4 + 2] = d2 * rs * sm[OFF_LN1 + 2] + sm[OFF_LN1 + 6];
            sx[n * 4 + 3] = d3 * rs * sm[OFF_LN1 + 3] + sm[OFF_LN1 + 7];
        }
        __syncthreads();

        // ---- P2: r = relu(x @ W1 + b1) ----
        for (int idx = htid; idx < NN * HID; idx += 64) {
            int n = idx >> 7, j = idx & 127;
            float u = sm[OFF_B1 + j];
            u = fmaf(sx[n * 4 + 0], sm[OFF_W1 + 0 * HID + j], u);
            u = fmaf(sx[n * 4 + 1], sm[OFF_W1 + 1 * HID + j], u);
            u = fmaf(sx[n * 4 + 2], sm[OFF_W1 + 2 * HID + j], u);
            u = fmaf(sx[n * 4 + 3], sm[OFF_W1 + 3 * HID + j], u);
            sr[idx] = fmaxf(u, 0.f);
        }
        __syncthreads();

        // ---- P3: dominant GEMM in packed f32x2 ----
        if (w2 == 0) p3_rows<14>(sr, sh, sm + OFF_W2, sm + OFF_B2, 0, lane);
        else         p3_rows<13>(sr, sh, sm + OFF_W2, sm + OFF_B2, 1, lane);
        __syncthreads();

        // ---- P4: LayerNorm(128) per row (warp per row, even/odd split) ----
        for (int n = w2; n < NN; n += 2) {
            float4 v = ((float4*)sh)[n * 32 + lane];
            float s  = v.x + v.y + v.z + v.w;
            float s2 = v.x * v.x + v.y * v.y + v.z * v.z + v.w * v.w;
#pragma unroll
            for (int off = 16; off >= 1; off >>= 1) {
                s  += __shfl_xor_sync(0xffffffffu, s,  off);
                s2 += __shfl_xor_sync(0xffffffffu, s2, off);
            }
            float mu  = s  * (1.f / 128.f);
            float var = s2 * (1.f / 128.f) - mu * mu;
            float rs  = rsqrtf(var + 1e-5f);
            float4 g  = ((const float4*)(sm + OFF_G2))[lane];
            float4 be = ((const float4*)(sm + OFF_BB2))[lane];
            float4 o;
            o.x = (v.x - mu) * rs * g.x + be.x;
            o.y = (v.y - mu) * rs * g.y + be.y;
            o.z = (v.z - mu) * rs * g.z + be.z;
            o.w = (v.w - mu) * rs * g.w + be.w;
            ((float4*)sh)[n * 32 + lane] = o;
        }
        __syncthreads();

        // ---- P5: scores in packed f32x2, stored transposed [k][n] ----
        if (w2 == 0) p5_rows<14>(sh, sm + OFF_P, ssc, 0, lane, lane < NN);
        else         p5_rows<13>(sh, sm + OFF_P, ssc, 1, lane, lane < NN);
        __syncthreads();

        // ---- write transposed scores (coalesced) ----
        {
            float* dst = g_scores + (size_t)(4 * bq + q) * (NN * NN);
            for (int i = htid; i < NN * NN; i += 64) {
                int k = i / NN;
                int n = i - k * NN;
                dst[i] = ssc[k * 29 + n];
            }
        }
        __syncthreads();
    }
}

// ---------------- Sinkhorn: warp per TWO batches, packed f32x2 ----------------
// Lane = column n (lanes 27..31 hold zeros). p[k] holds (batch b0 | batch b1).
__global__ void __launch_bounds__(256)
k2_sinkhorn(const float* __restrict__ tau_r, float* __restrict__ out)
{
    const int warp = threadIdx.x >> 5;
    const int lane = threadIdx.x & 31;
    const int pi = blockIdx.x * 8 + warp;      // batch-pair index
    if (pi >= BB / 2) return;

    const float inv_tau = 1.0f / tau_r[0];
    const float* s0 = g_scores + (size_t)(2 * pi) * (NN * NN);
    const float* s1 = s0 + NN * NN;

    unsigned long long p[NN];
#pragma unroll
    for (int k = 0; k < NN; k++) {
        float v0 = 0.f, v1 = 0.f;
        if (lane < NN) {
            v0 = __expf(s0[k * NN + lane] * inv_tau);
            v1 = __expf(s1[k * NN + lane] * inv_tau);
        }
        p[k] = pk2(v0, v1);
    }

#pragma unroll 1
    for (int it = 0; it < SINK_ITERS; it++) {
        // row normalize: sum over n (across lanes)
#pragma unroll
        for (int k = 0; k < NN; k++) {
            unsigned long long s = p[k];
            unsigned long long t;
            t = __shfl_xor_sync(0xffffffffu, s, 16); PADD(s, s, t);
            t = __shfl_xor_sync(0xffffffffu, s, 8);  PADD(s, s, t);
            t = __shfl_xor_sync(0xffffffffu, s, 4);  PADD(s, s, t);
            t = __shfl_xor_sync(0xffffffffu, s, 2);  PADD(s, s, t);
            t = __shfl_xor_sync(0xffffffffu, s, 1);  PADD(s, s, t);
            float2 sv = unpk(s);
            unsigned long long inv = pk2(rcpa(sv.x), rcpa(sv.y));
            PMUL(p[k], p[k], inv);
        }
        // column normalize: sum over k (in-lane)
        unsigned long long c = p[0];
#pragma unroll
        for (int k = 1; k < NN; k++) PADD(c, c, p[k]);
        float2 cv = unpk(c);
        float cix = (lane < NN) ? rcpa(cv.x) : 0.f;   // keep dead lanes at 0
        float ciy = (lane < NN) ? rcpa(cv.y) : 0.f;
        unsigned long long ci = pk2(cix, ciy);
#pragma unroll
        for (int k = 0; k < NN; k++) PMUL(p[k], p[k], ci);
    }

    if (lane < NN) {
        float* d0 = out + (size_t)(2 * pi) * (NN * NN);
        float* d1 = d0 + NN * NN;
#pragma unroll
        for (int k = 0; k < NN; k++) {
            float2 v = unpk(p[k]);
            d0[k * NN + lane] = v.x;
            d1[k * NN + lane] = v.y;
        }
    }
}

extern "C" void kernel_launch(void* const* d_in, const int* in_sizes, int n_in,
                              void* d_out, int out_size)
{
    const float* A      = (const float*)d_in[0];
    const float* m_     = (const float*)d_in[1];
    const float* tau_r  = (const float*)d_in[2];
    const float* ln1_g  = (const float*)d_in[3];
    const float* ln1_b  = (const float*)d_in[4];
    const float* W1     = (const float*)d_in[5];
    const float* b1     = (const float*)d_in[6];
    const float* W2     = (const float*)d_in[7];
    const float* b2     = (const float*)d_in[8];
    const float* ln2_g  = (const float*)d_in[9];
    const float* ln2_b  = (const float*)d_in[10];
    const float* protos = (const float*)d_in[11];

    int smCount = 148;
    cudaDeviceGetAttribute(&smCount, cudaDevAttrMultiProcessorCount, 0);
    cudaFuncSetAttribute((const void*)k1_scores,
                         cudaFuncAttributeMaxDynamicSharedMemorySize, SMEM_BYTES);

    k1_scores<<<smCount, 256, SMEM_BYTES>>>(A, m_, ln1_g, ln1_b, W1, b1,
                                            W2, b2, ln2_g, ln2_b, protos);
    k2_sinkhorn<<<(BB / 2 + 7) / 8, 256>>>(tau_r, (float*)d_out);
}

// round 13
// speedup vs baseline: 1.0514x; 1.0514x over previous
#include <cuda_runtime.h>
#include <math.h>

#define BB   32768
#define NQUAD 8192
#define NN   27
#define HID  128
#define SINK_ITERS 20

__device__ float g_scores[(size_t)BB * NN * NN];

#define OFF_W2   0
#define OFF_W1   16384
#define OFF_B1   16896
#define OFF_B2   17024
#define OFF_G2   17152
#define OFF_BB2  17280
#define OFF_LN1  17408
#define OFF_M    17416
#define OFF_P    17524
#define P_STRIDE 132
#define OFF_BAT  21088
#define BO_A 0
#define BO_X 732
#define BO_R 844
#define BO_H 4300
#define BO_SC 7756
#define PB   8540
#define SMEM_FLOATS (OFF_BAT + 4*PB)
#define SMEM_BYTES  (SMEM_FLOATS * 4)

#define FFMA2ACC(d,a,b) asm("fma.rn.f32x2 %0, %1, %2, %0;" : "+l"(d) : "l"(a), "l"(b))

__device__ __forceinline__ unsigned long long dup2(float x) {
    unsigned long long r;
    asm("mov.b64 %0, {%1, %2};" : "=l"(r) : "f"(x), "f"(x));
    return r;
}
__device__ __forceinline__ float2 unpk(unsigned long long v) {
    float2 f;
    asm("mov.b64 {%0, %1}, %2;" : "=f"(f.x), "=f"(f.y) : "l"(v));
    return f;
}

template<int NR>
__device__ __forceinline__ void p3_rows(const float* __restrict__ srb,
                                        float* __restrict__ shb,
                                        const float* __restrict__ sW2,
                                        const float* __restrict__ sb2,
                                        int w2, int jq)
{
    const ulonglong2* W2v = (const ulonglong2*)sW2;
    unsigned long long aL[NR], aH[NR];
#pragma unroll
    for (int t = 0; t < NR; t++) { aL[t] = 0ull; aH[t] = 0ull; }
#pragma unroll 1
    for (int i = 0; i < HID; i += 4) {
        ulonglong2 w0 = W2v[(i + 0) * 32 + jq];
        ulonglong2 w1 = W2v[(i + 1) * 32 + jq];
        ulonglong2 w2v = W2v[(i + 2) * 32 + jq];
        ulonglong2 w3 = W2v[(i + 3) * 32 + jq];
#pragma unroll
        for (int t = 0; t < NR; t++) {
            const int n = w2 + 2 * t;
            float4 rq = *(const float4*)(srb + n * HID + i);
            unsigned long long r0 = dup2(rq.x), r1 = dup2(rq.y);
            unsigned long long r2 = dup2(rq.z), r3 = dup2(rq.w);
            FFMA2ACC(aL[t], r0, w0.x);  FFMA2ACC(aH[t], r0, w0.y);
            FFMA2ACC(aL[t], r1, w1.x);  FFMA2ACC(aH[t], r1, w1.y);
            FFMA2ACC(aL[t], r2, w2v.x); FFMA2ACC(aH[t], r2, w2v.y);
            FFMA2ACC(aL[t], r3, w3.x);  FFMA2ACC(aH[t], r3, w3.y);
        }
    }
    float4 bb = ((const float4*)sb2)[jq];
#pragma unroll
    for (int t = 0; t < NR; t++) {
        const int n = w2 + 2 * t;
        float2 lo = unpk(aL[t]), hi = unpk(aH[t]);
        float4 o;
        o.x = lo.x + bb.x; o.y = lo.y + bb.y;
        o.z = hi.x + bb.z; o.w = hi.y + bb.w;
        *(float4*)(shb + n * HID + 4 * jq) = o;
    }
}

template<int NR>
__device__ __forceinline__ void p5_rows(const float* __restrict__ shb,
                                        const float* __restrict__ sP,
                                        float* __restrict__ ssc,
                                        int w2, int k, bool kvalid)
{
    const int kk = kvalid ? k : (NN - 1);
    const ulonglong2* Pv = (const ulonglong2*)sP;
    unsigned long long acc[NR];
#pragma unroll
    for (int t = 0; t < NR; t++) acc[t] = 0ull;
#pragma unroll 1
    for (int jq = 0; jq < 32; jq++) {
        ulonglong2 pv = Pv[kk * 33 + jq];
#pragma unroll
        for (int t = 0; t < NR; t++) {
            const int n = w2 + 2 * t;
            ulonglong2 hv = *(const ulonglong2*)(shb + n * HID + 4 * jq);
            FFMA2ACC(acc[t], hv.x, pv.x);
            FFMA2ACC(acc[t], hv.y, pv.y);
        }
    }
    if (kvalid) {
#pragma unroll
        for (int t = 0; t < NR; t++) {
            float2 s = unpk(acc[t]);
            ssc[k * 29 + (w2 + 2 * t)] = s.x + s.y;
        }
    }
}

__global__ void __launch_bounds__(256, 1)
k1_scores(const float* __restrict__ A,
          const float* __restrict__ m_,
          const float* __restrict__ ln1_g, const float* __restrict__ ln1_b,
          const float* __restrict__ W1,    const float* __restrict__ b1,
          const float* __restrict__ W2,    const float* __restrict__ b2,
          const float* __restrict__ ln2_g, const float* __restrict__ ln2_b,
          const float* __restrict__ protos)
{
    extern __shared__ float sm[];
    const int tid  = threadIdx.x;
    const int lane = tid & 31;
    const int q    = tid >> 6;
    const int htid = tid & 63;
    const int w2   = (tid >> 5) & 1;

    for (int i = tid; i < HID * HID; i += 256) sm[OFF_W2 + i] = W2[i];
    for (int i = tid; i < 4 * HID; i += 256)   sm[OFF_W1 + i] = W1[i];
    if (tid < HID) {
        sm[OFF_B1 + tid]  = b1[tid];
        sm[OFF_B2 + tid]  = b2[tid];
        sm[OFF_G2 + tid]  = ln2_g[tid];
        sm[OFF_BB2 + tid] = ln2_b[tid];
    }
    if (tid < 4) { sm[OFF_LN1 + tid] = ln1_g[tid]; sm[OFF_LN1 + 4 + tid] = ln1_b[tid]; }
    for (int i = tid; i < NN * HID; i += 256)
        sm[OFF_P + (i >> 7) * P_STRIDE + (i & 127)] = protos[i];
    __syncthreads();

    int jj[12], oo[12];
#pragma unroll
    for (int u = 0; u < 12; u++) {
        int idx = tid + 256 * u;
        jj[u] = idx / (NN * NN);
        oo[u] = idx - jj[u] * (NN * NN);
    }

    float pf[12];
    float mreg = 0.f;
    int bq = blockIdx.x;
    {
        const float* src = A + (size_t)bq * (4 * NN * NN);
#pragma unroll
        for (int u = 0; u < 12; u++) {
            int idx = tid + 256 * u;
            pf[u] = (idx < 4 * NN * NN) ? src[idx] : 0.f;
        }
        if (tid < 4 * NN) mreg = m_[(size_t)bq * 4 * NN + tid];
    }

    for (; bq < NQUAD; bq += (int)gridDim.x) {
#pragma unroll
        for (int u = 0; u < 12; u++) {
            int idx = tid + 256 * u;
            if (idx < 4 * NN * NN)
                sm[OFF_BAT + jj[u] * PB + BO_A + oo[u]] = pf[u];
        }
        if (tid < 4 * NN) sm[OFF_M + tid] = mreg;
        __syncthreads();

        {
            int bqn = bq + (int)gridDim.x;
            if (bqn < NQUAD) {
                const float* src = A + (size_t)bqn * (4 * NN * NN);
#pragma unroll
                for (int u = 0; u < 12; u++) {
                    int idx = tid + 256 * u;
                    pf[u] = (idx < 4 * NN * NN) ? src[idx] : 0.f;
                }
                if (tid < 4 * NN) mreg = m_[(size_t)bqn * 4 * NN + tid];
            }
        }

        float* sB  = sm + OFF_BAT + q * PB;
        float* sA  = sB + BO_A;
        float* sx  = sB + BO_X;
        float* sr  = sB + BO_R;
        float* sh  = sB + BO_H;
        float* ssc = sB + BO_SC;

        if (htid < NN) {
            const int n = htid;
            float s = 0.f, t1 = 0.f, t2 = 0.f;
#pragma unroll
            for (int j = 0; j < NN; j++) {
                float a = sA[n * NN + j];
                s += a;
                float v = (j == n) ? 0.0f : a;
                if (v > t1) { t2 = t1; t1 = v; }
                else if (v > t2) { t2 = v; }
            }
            float f0 = log1pf(s);
            float f3 = sm[OFF_M + q * NN + n];
            float mu = 0.25f * (f0 + t1 + t2 + f3);
            float d0 = f0 - mu, d1 = t1 - mu, d2 = t2 - mu, d3 = f3 - mu;
            float var = 0.25f * (d0 * d0 + d1 * d1 + d2 * d2 + d3 * d3);
            float rs = rsqrtf(var + 1e-5f);
            sx[n * 4 + 0] = d0 * rs * sm[OFF_LN1 + 0] + sm[OFF_LN1 + 4];
            sx[n * 4 + 1] = d1 * rs * sm[OFF_LN1 + 1] + sm[OFF_LN1 + 5];
            sx[n * 4 + 2] = d2 * rs * sm[OFF_LN1 + 2] + sm[OFF_LN1 + 6];
            sx[n * 4 + 3] = d3 * rs * sm[OFF_LN1 + 3] + sm[OFF_LN1 + 7];
        }
        __syncthreads();

        for (int idx = htid; idx < NN * HID; idx += 64) {
            int n = idx >> 7, j = idx & 127;
            float u = sm[OFF_B1 + j];
            u = fmaf(sx[n * 4 + 0], sm[OFF_W1 + 0 * HID + j], u);
            u = fmaf(sx[n * 4 + 1], sm[OFF_W1 + 1 * HID + j], u);
            u = fmaf(sx[n * 4 + 2], sm[OFF_W1 + 2 * HID + j], u);
            u = fmaf(sx[n * 4 + 3], sm[OFF_W1 + 3 * HID + j], u);
            sr[idx] = fmaxf(u, 0.f);
        }
        __syncthreads();

        if (w2 == 0) p3_rows<14>(sr, sh, sm + OFF_W2, sm + OFF_B2, 0, lane);
        else         p3_rows<13>(sr, sh, sm + OFF_W2, sm + OFF_B2, 1, lane);
        __syncthreads();

        for (int n = w2; n < NN; n += 2) {
            float4 v = ((float4*)sh)[n * 32 + lane];
            float s  = v.x + v.y + v.z + v.w;
            float s2 = v.x * v.x + v.y * v.y + v.z * v.z + v.w * v.w;
#pragma unroll
            for (int off = 16; off >= 1; off >>= 1) {
                s  += __shfl_xor_sync(0xffffffffu, s,  off);
                s2 += __shfl_xor_sync(0xffffffffu, s2, off);
            }
            float mu  = s  * (1.f / 128.f);
            float var = s2 * (1.f / 128.f) - mu * mu;
            float rs  = rsqrtf(var + 1e-5f);
            float4 g  = ((const float4*)(sm + OFF_G2))[lane];
            float4 be = ((const float4*)(sm + OFF_BB2))[lane];
            float4 o;
            o.x = (v.x - mu) * rs * g.x + be.x;
            o.y = (v.y - mu) * rs * g.y + be.y;
            o.z = (v.z - mu) * rs * g.z + be.z;
            o.w = (v.w - mu) * rs * g.w + be.w;
            ((float4*)sh)[n * 32 + lane] = o;
        }
        __syncthreads();

        if (w2 == 0) p5_rows<14>(sh, sm + OFF_P, ssc, 0, lane, lane < NN);
        else         p5_rows<13>(sh, sm + OFF_P, ssc, 1, lane, lane < NN);
        __syncthreads();

        {
            float* dst = g_scores + (size_t)(4 * bq + q) * (NN * NN);
            for (int i = htid; i < NN * NN; i += 64) {
                int k = i / NN;
                int n = i - k * NN;
                dst[i] = ssc[k * 29 + n];
            }
        }
        __syncthreads();
    }
}

// Sinkhorn: warp per batch, scalar (measured 347us in R3/R4)
__global__ void __launch_bounds__(256)
k2_sinkhorn(const float* __restrict__ tau_r, float* __restrict__ out)
{
    const int warp = threadIdx.x >> 5;
    const int lane = threadIdx.x & 31;
    const int b = blockIdx.x * 8 + warp;
    if (b >= BB) return;

    const float inv_tau = 1.0f / tau_r[0];
    const float* src = g_scores + (size_t)b * (NN * NN);

    float p[NN];
#pragma unroll
    for (int k = 0; k < NN; k++) {
        float v = (lane < NN) ? src[k * NN + lane] : 0.f;
        p[k] = (lane < NN) ? __expf(v * inv_tau) : 0.f;
    }

#pragma unroll 1
    for (int it = 0; it < SINK_ITERS; it++) {
#pragma unroll
        for (int k = 0; k < NN; k++) {
            float s = p[k];
            s += __shfl_xor_sync(0xffffffffu, s, 16);
            s += __shfl_xor_sync(0xffffffffu, s, 8);
            s += __shfl_xor_sync(0xffffffffu, s, 4);
            s += __shfl_xor_sync(0xffffffffu, s, 2);
            s += __shfl_xor_sync(0xffffffffu, s, 1);
            p[k] *= __fdividef(1.f, s);
        }
        float c = 0.f;
#pragma unroll
        for (int k = 0; k < NN; k++) c += p[k];
        float ci = (lane < NN) ? __fdividef(1.f, c) : 0.f;
#pragma unroll
        for (int k = 0; k < NN; k++) p[k] *= ci;
    }

    float* dst = out + (size_t)b * (NN * NN);
    if (lane < NN) {
#pragma unroll
        for (int k = 0; k < NN; k++) dst[k * NN + lane] = p[k];
    }
}

extern "C" void kernel_launch(void* const* d_in, const int* in_sizes, int n_in,
                              void* d_out, int out_size)
{
    const float* A      = (const float*)d_in[0];
    const float* m_     = (const float*)d_in[1];
    const float* tau_r  = (const float*)d_in[2];
    const float* ln1_g  = (const float*)d_in[3];
    const float* ln1_b  = (const float*)d_in[4];
    const float* W1     = (const float*)d_in[5];
    const float* b1     = (const float*)d_in[6];
    const float* W2     = (const float*)d_in[7];
    const float* b2     = (const float*)d_in[8];
    const float* ln2_g  = (const float*)d_in[9];
    const float* ln2_b  = (const float*)d_in[10];
    const float* protos = (const float*)d_in[11];

    int smCount = 148;
    cudaDeviceGetAttribute(&smCount, cudaDevAttrMultiProcessorCount, 0);
    cudaFuncSetAttribute((const void*)k1_scores,
                         cudaFuncAttributeMaxDynamicSharedMemorySize, SMEM_BYTES);

    k1_scores<<<smCount, 256, SMEM_BYTES>>>(A, m_, ln1_g, ln1_b, W1, b1,
                                            W2, b2, ln2_g, ln2_b, protos);
    k2_sinkhorn<<<(BB + 7) / 8, 256>>>(tau_r, (float*)d_out);
}

// round 14
// speedup vs baseline: 1.1710x; 1.1138x over previous
#include <cuda_runtime.h>
#include <math.h>

#define BB 32768
#define NQUAD 8192
#define NN 27
#define HID 128
#define SINK_ITERS 20

__device__ float g_scores[(size_t)BB * NN * NN];

// ---- smem float offsets ----
#define OFF_W2  0        // 128x128, [i][j]
#define OFF_W1  16384    // [c][i] 4x128
#define OFF_B1  16896
#define OFF_B2  17024
#define OFF_LN1 17152    // 8
#define OFF_M   17160    // 108
#define OFF_CK  17268    // 32
#define OFF_SK  17300    // 32
#define OFF_BPK 17332    // 32
#define OFF_WPT 17364    // Wp^T [k][i] stride 132 : 27*132 = 3564
#define OFF_BAT 20928
// slab sub-offsets (per batch-in-quad), SLAB floats each
#define SB_A   0         // A 729 (overlaps SR region; A consumed in P1 before P2 writes SR)
#define SB_SR  0         // r row-major 28x128 = 3584
#define SB_X   3584      // 28x4 = 112
#define SB_SRT 3696      // r transposed [i][n] 128x30 = 3840
#define SB_SSC 7536      // 27x29 = 783
#define SLAB   8320
#define SMEM_FLOATS (OFF_BAT + 4 * SLAB)
#define SMEM_BYTES  (SMEM_FLOATS * 4)   // 216,832 B

#define FFMA2ACC(d,a,b) asm("fma.rn.f32x2 %0, %1, %2, %0;" : "+l"(d) : "l"(a), "l"(b))
#define PADD(d,a,b)     asm("add.rn.f32x2 %0, %1, %2;" : "=l"(d) : "l"(a), "l"(b))

__device__ __forceinline__ unsigned long long dup2(float x) {
    unsigned long long r;
    asm("mov.b64 %0, {%1, %2};" : "=l"(r) : "f"(x), "f"(x));
    return r;
}
__device__ __forceinline__ float2 unpk(unsigned long long v) {
    float2 f;
    asm("mov.b64 {%0, %1}, %2;" : "=f"(f.x), "=f"(f.y) : "l"(v));
    return f;
}

__global__ void __launch_bounds__(256, 1)
k1_scores(const float* __restrict__ A, const float* __restrict__ m_,
          const float* __restrict__ ln1_g, const float* __restrict__ ln1_b,
          const float* __restrict__ W1, const float* __restrict__ b1,
          const float* __restrict__ W2, const float* __restrict__ b2,
          const float* __restrict__ ln2_g, const float* __restrict__ ln2_b,
          const float* __restrict__ protos)
{
    extern __shared__ float sm[];
    const int tid  = threadIdx.x;
    const int lane = tid & 31;
    const int q    = tid >> 6;          // batch-in-quad
    const int htid = tid & 63;
    const int w2   = (tid >> 5) & 1;    // warp within quarter
    const int base = w2 * 14;           // rows base (row 27 is padding)

    // ---- one-time param staging ----
    for (int i = tid; i < HID * HID; i += 256) sm[OFF_W2 + i] = W2[i];
    for (int i = tid; i < 4 * HID; i += 256)   sm[OFF_W1 + i] = W1[i];
    if (tid < HID) {
        sm[OFF_B1 + tid] = b1[tid];
        sm[OFF_B2 + tid] = b2[tid];
        sm[OFF_BAT + 4000 + tid] = ln2_g[tid];   // temp g
        sm[OFF_BAT + 4128 + tid] = ln2_b[tid];   // temp b
    }
    if (tid < 4) { sm[OFF_LN1 + tid] = ln1_g[tid]; sm[OFF_LN1 + 4 + tid] = ln1_b[tid]; }
    __syncthreads();

    // pg[k][j] = g[j]*protos[k][j], stride 129 (conflict-free column reads)
    for (int idx = tid; idx < NN * HID; idx += 256) {
        int k = idx >> 7, j = idx & 127;
        sm[OFF_BAT + k * 129 + j] = protos[idx] * sm[OFF_BAT + 4000 + j];
    }
    __syncthreads();
    // WpT[k][i] = sum_j W2[i][j]*pg[k][j]  (stride 132)
    for (int idx = tid; idx < NN * HID; idx += 256) {
        int k = idx % NN, i = idx / NN;
        float acc = 0.f;
        const float* w2r = sm + OFF_W2 + i * HID;
        const float* pgr = sm + OFF_BAT + k * 129;
        for (int j = 0; j < HID; j++) acc = fmaf(w2r[j], pgr[j], acc);
        sm[OFF_WPT + k * 132 + i] = acc;
    }
    // S_k, c_k, bp_k
    if (tid < NN) {
        float S = 0.f, c = 0.f, bp = 0.f;
        const float* pgr = sm + OFF_BAT + tid * 129;
        for (int j = 0; j < HID; j++) {
            float p = pgr[j];
            S += p;
            c = fmaf(sm[OFF_B2 + j], p, c);
            bp = fmaf(sm[OFF_BAT + 4128 + j], protos[tid * HID + j], bp);
        }
        sm[OFF_SK + tid] = S; sm[OFF_CK + tid] = c; sm[OFF_BPK + tid] = bp;
    }
    __syncthreads();
    // zero x pad row 27 of each slab (never written by P1)
    if (tid < 16) sm[OFF_BAT + (tid >> 2) * SLAB + SB_X + NN * 4 + (tid & 3)] = 0.f;
    __syncthreads();

    // A prefetch scatter map
    int jj[12], oo[12];
#pragma unroll
    for (int u = 0; u < 12; u++) {
        int idx = tid + 256 * u;
        jj[u] = idx / (NN * NN);
        oo[u] = idx - jj[u] * (NN * NN);
    }
    float pf[12]; float mreg = 0.f;
    int bq = blockIdx.x;
    {
        const float* src = A + (size_t)bq * (4 * NN * NN);
#pragma unroll
        for (int u = 0; u < 12; u++) {
            int idx = tid + 256 * u;
            pf[u] = (idx < 4 * NN * NN) ? src[idx] : 0.f;
        }
        if (tid < 4 * NN) mreg = m_[(size_t)bq * 4 * NN + tid];
    }

    for (; bq < NQUAD; bq += (int)gridDim.x) {
#pragma unroll
        for (int u = 0; u < 12; u++) {
            int idx = tid + 256 * u;
            if (idx < 4 * NN * NN)
                sm[OFF_BAT + jj[u] * SLAB + SB_A + oo[u]] = pf[u];
        }
        if (tid < 4 * NN) sm[OFF_M + tid] = mreg;
        __syncthreads();

        {   // prefetch next quad
            int bqn = bq + (int)gridDim.x;
            if (bqn < NQUAD) {
                const float* src = A + (size_t)bqn * (4 * NN * NN);
#pragma unroll
                for (int u = 0; u < 12; u++) {
                    int idx = tid + 256 * u;
                    pf[u] = (idx < 4 * NN * NN) ? src[idx] : 0.f;
                }
                if (tid < 4 * NN) mreg = m_[(size_t)bqn * 4 * NN + tid];
            }
        }

        float* slab = sm + OFF_BAT + q * SLAB;

        // ---- P1: features + LN1 ----
        if (tid < 4 * NN) {
            const int qq = tid / NN, n = tid - qq * NN;
            const float* sA = sm + OFF_BAT + qq * SLAB + SB_A + n * NN;
            float s = 0.f, t1 = 0.f, t2 = 0.f;
#pragma unroll
            for (int j = 0; j < NN; j++) {
                float a = sA[j];
                s += a;
                float v = (j == n) ? 0.f : a;
                if (v > t1) { t2 = t1; t1 = v; } else if (v > t2) t2 = v;
            }
            float f0 = log1pf(s), f3 = sm[OFF_M + tid];
            float mu = 0.25f * (f0 + t1 + t2 + f3);
            float d0 = f0 - mu, d1 = t1 - mu, d2 = t2 - mu, d3 = f3 - mu;
            float rs = rsqrtf(0.25f * (d0*d0 + d1*d1 + d2*d2 + d3*d3) + 1e-5f);
            float* x = sm + OFF_BAT + qq * SLAB + SB_X + n * 4;
            x[0] = d0 * rs * sm[OFF_LN1 + 0] + sm[OFF_LN1 + 4];
            x[1] = d1 * rs * sm[OFF_LN1 + 1] + sm[OFF_LN1 + 5];
            x[2] = d2 * rs * sm[OFF_LN1 + 2] + sm[OFF_LN1 + 6];
            x[3] = d3 * rs * sm[OFF_LN1 + 3] + sm[OFF_LN1 + 7];
        }
        __syncthreads();

        // ---- P2: r = relu(x@W1+b1) -> sr (row-major) AND srT ([i][n] stride 30) ----
        {
            const int n = htid & 31, ib = htid >> 5;
            if (n < 28) {
                const float* x = slab + SB_X + n * 4;
                float x0 = x[0], x1 = x[1], x2 = x[2], x3 = x[3];
#pragma unroll 1
                for (int it = 0; it < 16; it++) {
                    int i0 = ib * 64 + 4 * ((it + n) & 15);   // skewed to spread store banks
                    float4 wa = *(const float4*)(sm + OFF_W1 + 0 * HID + i0);
                    float4 wb = *(const float4*)(sm + OFF_W1 + 1 * HID + i0);
                    float4 wc = *(const float4*)(sm + OFF_W1 + 2 * HID + i0);
                    float4 wd = *(const float4*)(sm + OFF_W1 + 3 * HID + i0);
                    float4 bb = *(const float4*)(sm + OFF_B1 + i0);
                    float4 r;
                    r.x = fmaxf(bb.x + x0*wa.x + x1*wb.x + x2*wc.x + x3*wd.x, 0.f);
                    r.y = fmaxf(bb.y + x0*wa.y + x1*wb.y + x2*wc.y + x3*wd.y, 0.f);
                    r.z = fmaxf(bb.z + x0*wa.z + x1*wb.z + x2*wc.z + x3*wd.z, 0.f);
                    r.w = fmaxf(bb.w + x0*wa.w + x1*wb.w + x2*wc.w + x3*wd.w, 0.f);
                    *(float4*)(slab + SB_SR + n * HID + i0) = r;
                    slab[SB_SRT + (i0 + 0) * 30 + n] = r.x;
                    slab[SB_SRT + (i0 + 1) * 30 + n] = r.y;
                    slab[SB_SRT + (i0 + 2) * 30 + n] = r.z;
                    slab[SB_SRT + (i0 + 3) * 30 + n] = r.w;
                }
            }
        }
        __syncthreads();

        // ---- P3: h-GEMM (row-pair f32x2) with inline moment accumulation ----
        float mu[14], rs[14];
        {
            unsigned long long acc[7][4];
#pragma unroll
            for (int t = 0; t < 7; t++)
#pragma unroll
                for (int c = 0; c < 4; c++) acc[t][c] = 0ull;
            const float* srt = slab + SB_SRT + base;
#pragma unroll 4
            for (int i = 0; i < HID; i++) {
                float4 w = *(const float4*)(sm + OFF_W2 + i * HID + 4 * lane);
                unsigned long long wd0 = dup2(w.x), wd1 = dup2(w.y);
                unsigned long long wd2 = dup2(w.z), wd3 = dup2(w.w);
#pragma unroll
                for (int t = 0; t < 7; t++) {
                    unsigned long long rp = *(const unsigned long long*)(srt + i * 30 + 2 * t);
                    FFMA2ACC(acc[t][0], rp, wd0);
                    FFMA2ACC(acc[t][1], rp, wd1);
                    FFMA2ACC(acc[t][2], rp, wd2);
                    FFMA2ACC(acc[t][3], rp, wd3);
                }
            }
            // add b2, accumulate s/s2 per row
            float s[14], s2[14];
#pragma unroll
            for (int r = 0; r < 14; r++) { s[r] = 0.f; s2[r] = 0.f; }
            unsigned long long bd[4];
#pragma unroll
            for (int c = 0; c < 4; c++) bd[c] = dup2(sm[OFF_B2 + 4 * lane + c]);
#pragma unroll
            for (int t = 0; t < 7; t++)
#pragma unroll
                for (int c = 0; c < 4; c++) {
                    unsigned long long v;
                    PADD(v, acc[t][c], bd[c]);
                    float2 f = unpk(v);
                    s[2*t]   += f.x;  s2[2*t]   = fmaf(f.x, f.x, s2[2*t]);
                    s[2*t+1] += f.y;  s2[2*t+1] = fmaf(f.y, f.y, s2[2*t+1]);
                }
            // warp all-reduce per row -> mu, rs in every lane
#pragma unroll
            for (int r = 0; r < 14; r++) {
                float a = s[r], b = s2[r];
#pragma unroll
                for (int off = 16; off >= 1; off >>= 1) {
                    a += __shfl_xor_sync(0xffffffffu, a, off);
                    b += __shfl_xor_sync(0xffffffffu, b, off);
                }
                float m = a * (1.f / 128.f);
                mu[r] = m;
                rs[r] = rsqrtf(b * (1.f / 128.f) - m * m + 1e-5f);
            }
        }

        // ---- P5: scores via r.Wp (lane = k), same warp rows, no barrier needed ----
        {
            const int kk = (lane < NN) ? lane : (NN - 1);
            const float ckv = sm[OFF_CK + kk];
            const float skv = sm[OFF_SK + kk];
            const float bpv = sm[OFF_BPK + kk];
            const ulonglong2* Wv = (const ulonglong2*)(sm + OFF_WPT);
            const float* srr = slab + SB_SR + base * HID;
            unsigned long long a5[14];
#pragma unroll
            for (int n = 0; n < 14; n++) a5[n] = 0ull;
#pragma unroll 1
            for (int jq = 0; jq < 32; jq++) {
                ulonglong2 wv = Wv[kk * 33 + jq];
#pragma unroll
                for (int n = 0; n < 14; n++) {
                    ulonglong2 hv = *(const ulonglong2*)(srr + n * HID + 4 * jq);
                    FFMA2ACC(a5[n], hv.x, wv.x);
                    FFMA2ACC(a5[n], hv.y, wv.y);
                }
            }
            if (lane < NN) {
#pragma unroll
                for (int n = 0; n < 14; n++) {
                    if (base + n < NN) {
                        float2 f = unpk(a5[n]);
                        float dot = f.x + f.y;
                        float sc = rs[n] * (dot + ckv - mu[n] * skv) + bpv;
                        slab[SB_SSC + lane * 29 + base + n] = sc;
                    }
                }
            }
        }
        __syncthreads();

        {   // coalesced write of transposed scores
            float* dst = g_scores + (size_t)(4 * bq) * (NN * NN);
            for (int i = tid; i < 4 * NN * NN; i += 256) {
                int qq = i / (NN * NN), rem = i - qq * (NN * NN);
                int k = rem / NN, n = rem - k * NN;
                dst[i] = sm[OFF_BAT + qq * SLAB + SB_SSC + k * 29 + n];
            }
        }
        __syncthreads();
    }
}

// ---- Sinkhorn: warp per batch, scalar (measured 347us) ----
__global__ void __launch_bounds__(256)
k2_sinkhorn(const float* __restrict__ tau_r, float* __restrict__ out)
{
    const int warp = threadIdx.x >> 5;
    const int lane = threadIdx.x & 31;
    const int b = blockIdx.x * 8 + warp;
    if (b >= BB) return;

    const float inv_tau = 1.0f / tau_r[0];
    const float* src = g_scores + (size_t)b * (NN * NN);

    float p[NN];
#pragma unroll
    for (int k = 0; k < NN; k++) {
        float v = (lane < NN) ? src[k * NN + lane] : 0.f;
        p[k] = (lane < NN) ? __expf(v * inv_tau) : 0.f;
    }
#pragma unroll 1
    for (int it = 0; it < SINK_ITERS; it++) {
#pragma unroll
        for (int k = 0; k < NN; k++) {
            float s = p[k];
            s += __shfl_xor_sync(0xffffffffu, s, 16);
            s += __shfl_xor_sync(0xffffffffu, s, 8);
            s += __shfl_xor_sync(0xffffffffu, s, 4);
            s += __shfl_xor_sync(0xffffffffu, s, 2);
            s += __shfl_xor_sync(0xffffffffu, s, 1);
            p[k] *= __fdividef(1.f, s);
        }
        float c = 0.f;
#pragma unroll
        for (int k = 0; k < NN; k++) c += p[k];
        float ci = (lane < NN) ? __fdividef(1.f, c) : 0.f;
#pragma unroll
        for (int k = 0; k < NN; k++) p[k] *= ci;
    }
    float* dst = out + (size_t)b * (NN * NN);
    if (lane < NN) {
#pragma unroll
        for (int k = 0; k < NN; k++) dst[k * NN + lane] = p[k];
    }
}

extern "C" void kernel_launch(void* const* d_in, const int* in_sizes, int n_in,
                              void* d_out, int out_size)
{
    const float* A      = (const float*)d_in[0];
    const float* m_     = (const float*)d_in[1];
    const float* tau_r  = (const float*)d_in[2];
    const float* ln1_g  = (const float*)d_in[3];
    const float* ln1_b  = (const float*)d_in[4];
    const float* W1     = (const float*)d_in[5];
    const float* b1     = (const float*)d_in[6];
    const float* W2     = (const float*)d_in[7];
    const float* b2     = (const float*)d_in[8];
    const float* ln2_g  = (const float*)d_in[9];
    const float* ln2_b  = (const float*)d_in[10];
    const float* protos = (const float*)d_in[11];

    int smCount = 148;
    cudaDeviceGetAttribute(&smCount, cudaDevAttrMultiProcessorCount, 0);
    cudaFuncSetAttribute((const void*)k1_scores,
                         cudaFuncAttributeMaxDynamicSharedMemorySize, SMEM_BYTES);

    k1_scores<<<smCount, 256, SMEM_BYTES>>>(A, m_, ln1_g, ln1_b, W1, b1,
                                            W2, b2, ln2_g, ln2_b, protos);
    k2_sinkhorn<<<(BB + 7) / 8, 256>>>(tau_r, (float*)d_out);
}